// round 5
// baseline (speedup 1.0000x reference)
#include <cuda_runtime.h>
#include <cuda_bf16.h>

// Fixed-shape problem: N=2000 nodes, F=2, HIDDEN=64, K=3, G=256 graphs, E~7998 edges
#define NN    2000
#define EMAXS 8192          // smem edge capacity (actual E ~7998)
#define HID   64
#define TPB   1024

typedef unsigned long long ull;

// ---------------- f32x2 packed-math helpers ----------------
__device__ __forceinline__ ull pk2(float lo, float hi) {
    ull r; asm("mov.b64 %0,{%1,%2};" : "=l"(r) : "f"(lo), "f"(hi)); return r;
}
__device__ __forceinline__ void upk2(ull v, float& lo, float& hi) {
    asm("mov.b64 {%0,%1}, %2;" : "=f"(lo), "=f"(hi) : "l"(v));
}
__device__ __forceinline__ ull fma2v(ull a, ull b, ull c) {
    ull d; asm("fma.rn.f32x2 %0, %1, %2, %3;" : "=l"(d) : "l"(a), "l"(b), "l"(c)); return d;
}

// ---------------- device-global scratch ----------------
__device__ int  g_ptr[NN + 1];
__device__ int  g_perm[NN];
__device__ int2 g_edge[EMAXS];   // .x = src slot, .y = bits of gcn_norm weight

// ---------------- fused prepass (unchanged) ----------------
__global__ __launch_bounds__(1024)
void k_pre(const int* __restrict__ row, const int* __restrict__ col,
           const float* __restrict__ ew, int E) {
    __shared__ float sdeg[NN];
    __shared__ int   scnt[NN];
    __shared__ int   sinv[NN];
    __shared__ int   scur[NN];
    __shared__ int   hist[64];
    __shared__ int   hoff[64];
    __shared__ int   warpsum[32];
    const int t = threadIdx.x;

    for (int i = t; i < NN; i += 1024) { sdeg[i] = 0.f; scnt[i] = 0; }
    if (t < 64) hist[t] = 0;
    __syncthreads();

    for (int e = t; e < E; e += 1024) {
        int c = col[e];
        atomicAdd(&sdeg[c], ew[e]);
        atomicAdd(&scnt[c], 1);
    }
    __syncthreads();

    for (int n = t; n < NN; n += 1024) {
        int d = scnt[n]; if (d > 63) d = 63;
        atomicAdd(&hist[d], 1);
    }
    __syncthreads();
    if (t == 0) {
        int run = 0;
        for (int d = 0; d < 64; d++) { hoff[d] = run; run += hist[d]; }
    }
    __syncthreads();

    for (int n = t; n < NN; n += 1024) {
        int d = scnt[n]; int dc = (d > 63) ? 63 : d;
        int slot = atomicAdd(&hoff[dc], 1);
        sinv[n] = slot;
        g_perm[slot] = n;
        scur[slot] = d;
    }
    __syncthreads();

    {   // exclusive scan of slot-degrees -> g_ptr / scur cursors
        int i0 = 2 * t, i1 = 2 * t + 1;
        int a0 = (i0 < NN) ? scur[i0] : 0;
        int a1 = (i1 < NN) ? scur[i1] : 0;
        int tot = a0 + a1;
        int lane = t & 31, wid = t >> 5;
        int v = tot;
        #pragma unroll
        for (int o = 1; o < 32; o <<= 1) {
            int u = __shfl_up_sync(0xFFFFFFFFu, v, o);
            if (lane >= o) v += u;
        }
        if (lane == 31) warpsum[wid] = v;
        __syncthreads();
        if (wid == 0) {
            int w = warpsum[lane];
            #pragma unroll
            for (int o = 1; o < 32; o <<= 1) {
                int u = __shfl_up_sync(0xFFFFFFFFu, w, o);
                if (lane >= o) w += u;
            }
            warpsum[lane] = w;
        }
        __syncthreads();
        int base = v - tot + (wid ? warpsum[wid - 1] : 0);
        if (i0 < NN) { scur[i0] = base;      g_ptr[i0] = base; }
        if (i1 < NN) { scur[i1] = base + a0; g_ptr[i1] = base + a0; }
        if (t == 0)  g_ptr[NN] = E;
    }
    __syncthreads();

    for (int e = t; e < E; e += 1024) {
        int r = row[e], c = col[e];
        float dr = sdeg[r], dc = sdeg[c];
        float ir = (dr > 0.f) ? rsqrtf(dr) : 0.f;
        float ic = (dc > 0.f) ? rsqrtf(dc) : 0.f;
        float nrm = ir * ew[e] * ic;
        int p = atomicAdd(&scur[sinv[c]], 1);
        g_edge[p] = make_int2(sinv[r], __float_as_int(nrm));
    }
}

// ---------------- main fused kernel: one CTA per TWO graphs ----------------
// smem: 4 node buffers (ulonglong2 {gA pair, gB pair}) + edge CSR + weights + sptr
#define SMEM_BYTES (4 * NN * 16 + EMAXS * 8 + 2048 + 2048 + 256 + (NN + 1) * 4)

__global__ __launch_bounds__(TPB, 1)
void k_main(const float* __restrict__ x,
            const float* __restrict__ W1, const float* __restrict__ b1,
            const float* __restrict__ W2, const float* __restrict__ b2,
            float* __restrict__ out, int G, int E) {
    extern __shared__ float sm[];
    ulonglong2* pb0 = (ulonglong2*)sm;
    ulonglong2* pb1 = pb0 + NN;
    ulonglong2* pb2 = pb1 + NN;
    ulonglong2* pb3 = pb2 + NN;
    int2*  se  = (int2*)(pb3 + NN);        // staged edges
    float* w1q = (float*)(se + EMAXS);     // [32 jp][8 i][2 half]
    float* w2q = w1q + 512;                // [32 jp][2 jj][8 c]
    float* b1s = w2q + 512;
    int*   sptr = (int*)(b1s + 64);

    const int t  = threadIdx.x;
    const int bs = blockDim.x;
    const int gA = 2 * blockIdx.x;
    int gB = gA + 1; bool hasB = (gB < G); if (!hasB) gB = gA;

    // stage packed weights
    for (int i = t; i < 512; i += bs) {
        int jp = i >> 4, rem = i & 15;
        {   int ii = rem >> 1, half = rem & 1;
            w1q[i] = W1[ii * HID + 2 * jp + half]; }
        {   int jj = rem >> 3, c = rem & 7;
            int j = 2 * jp + jj;
            w2q[i] = W2[(c >> 1) * (HID * 2) + j * 2 + (c & 1)]; }
    }
    for (int i = t; i < HID; i += bs) b1s[i] = b1[i];
    for (int i = t; i < NN + 1; i += bs) sptr[i] = g_ptr[i];
    for (int i = t; i < E; i += bs) se[i] = g_edge[i];

    // stage x into slot space (permuted gather, both graphs) -> pb0
    const ull* xgA = (const ull*)(x + (size_t)gA * 2 * NN);
    const ull* xgB = (const ull*)(x + (size_t)gB * 2 * NN);
    for (int s = t; s < NN; s += bs) {
        int node = __ldg(&g_perm[s]);
        pb0[s] = make_ulonglong2(__ldg(&xgA[node]), __ldg(&xgB[node]));
    }
    __syncthreads();

    // ---- dual-node gather macro body (slots 2t, 2t+1; t < NN/2) ----
    #define GATHER2(PIN, POUT, ADD, USE_ADD)                                   \
    if (t < NN / 2) {                                                          \
        int s0 = 2 * t, s1 = s0 + 1;                                           \
        int b0 = sptr[s0], mid = sptr[s1], e1 = sptr[s1 + 1];                  \
        int d0 = mid - b0, d1 = e1 - mid;                                      \
        ull aA0 = 0, aB0 = 0, aA1 = 0, aB1 = 0;                                \
        if (USE_ADD) {                                                         \
            ulonglong2 z0 = ADD[s0]; aA0 = z0.x; aB0 = z0.y;                   \
            ulonglong2 z1 = ADD[s1]; aA1 = z1.x; aB1 = z1.y;                   \
        }                                                                      \
        int dm = (d0 > d1) ? d0 : d1;                                          \
        for (int k = 0; k < dm; k++) {                                         \
            if (k < d0) {                                                      \
                int2 ed = se[b0 + k];                                          \
                ull ww = pk2(__int_as_float(ed.y), __int_as_float(ed.y));      \
                ulonglong2 v = PIN[ed.x];                                      \
                aA0 = fma2v(v.x, ww, aA0); aB0 = fma2v(v.y, ww, aB0);          \
            }                                                                  \
            if (k < d1) {                                                      \
                int2 ed = se[mid + k];                                         \
                ull ww = pk2(__int_as_float(ed.y), __int_as_float(ed.y));      \
                ulonglong2 v = PIN[ed.x];                                      \
                aA1 = fma2v(v.x, ww, aA1); aB1 = fma2v(v.y, ww, aB1);          \
            }                                                                  \
        }                                                                      \
        POUT[s0] = make_ulonglong2(aA0, aB0);                                  \
        POUT[s1] = make_ulonglong2(aA1, aB1);                                  \
    }

    // layer-1 hops: p1=A p0, p2=A p1, p3=A p2
    GATHER2(pb0, pb1, pb0, false); __syncthreads();
    GATHER2(pb1, pb2, pb0, false); __syncthreads();
    GATHER2(pb2, pb3, pb0, false); __syncthreads();

    // ---- dense per-node sandwich, spill-free: 2 graph passes ----
    {
        const ulonglong2* w1v = (const ulonglong2*)w1q;
        const ulonglong2* w2v = (const ulonglong2*)w2q;
        const ull* b1v = (const ull*)b1s;
        ull* u0 = (ull*)pb0; ull* u1 = (ull*)pb1;
        ull* u2 = (ull*)pb2; ull* u3 = (ull*)pb3;
        #pragma unroll 1
        for (int gsel = 0; gsel < 2; gsel++) {
            #pragma unroll 1
            for (int n = t; n < NN; n += bs) {
                int idx = 2 * n + gsel;
                float f0, f1;
                upk2(u0[idx], f0, f1); ull p0 = pk2(f0, f0), p1 = pk2(f1, f1);
                upk2(u1[idx], f0, f1); ull p2 = pk2(f0, f0), p3 = pk2(f1, f1);
                upk2(u2[idx], f0, f1); ull p4 = pk2(f0, f0), p5 = pk2(f1, f1);
                upk2(u3[idx], f0, f1); ull p6 = pk2(f0, f0), p7 = pk2(f1, f1);
                ull m0 = 0, m1 = 0, m2 = 0, m3 = 0;
                #pragma unroll 4
                for (int jp = 0; jp < 32; jp++) {
                    ulonglong2 qa = w1v[jp * 4 + 0], qb = w1v[jp * 4 + 1];
                    ulonglong2 qc = w1v[jp * 4 + 2], qd = w1v[jp * 4 + 3];
                    ull h = b1v[jp];
                    h = fma2v(p0, qa.x, h); h = fma2v(p1, qa.y, h);
                    h = fma2v(p2, qb.x, h); h = fma2v(p3, qb.y, h);
                    h = fma2v(p4, qc.x, h); h = fma2v(p5, qc.y, h);
                    h = fma2v(p6, qd.x, h); h = fma2v(p7, qd.y, h);
                    float h0, h1; upk2(h, h0, h1);
                    h0 = fmaxf(h0, 0.f); h1 = fmaxf(h1, 0.f);
                    ull h0p = pk2(h0, h0), h1p = pk2(h1, h1);
                    ulonglong2 ra = w2v[jp * 4 + 0], rb = w2v[jp * 4 + 1];
                    ulonglong2 rc = w2v[jp * 4 + 2], rd = w2v[jp * 4 + 3];
                    m0 = fma2v(h0p, ra.x, m0); m1 = fma2v(h0p, ra.y, m1);
                    m2 = fma2v(h0p, rb.x, m2); m3 = fma2v(h0p, rb.y, m3);
                    m0 = fma2v(h1p, rc.x, m0); m1 = fma2v(h1p, rc.y, m1);
                    m2 = fma2v(h1p, rd.x, m2); m3 = fma2v(h1p, rd.y, m3);
                }
                u0[idx] = m0; u1[idx] = m1; u2[idx] = m2; u3[idx] = m3;
            }
        }
    }
    __syncthreads();

    // layer-2 Horner (in-place addends are safe: addend read only at own index):
    // pb2 <- m2 + A m3 ; pb1 <- m1 + A pb2
    GATHER2(pb3, pb2, pb2, true); __syncthreads();
    GATHER2(pb2, pb1, pb1, true); __syncthreads();

    // epilogue: out = x + m0 + A s + b2   (pin = pb1, add = pb0, + x reload)
    float b20 = b2[0], b21 = b2[1];
    float2* ogA = (float2*)out + (size_t)gA * NN;
    float2* ogB = (float2*)out + (size_t)gB * NN;
    if (t < NN / 2) {
        int s0 = 2 * t, s1 = s0 + 1;
        int b0 = sptr[s0], mid = sptr[s1], e1 = sptr[s1 + 1];
        int d0 = mid - b0, d1 = e1 - mid;
        int node0 = __ldg(&g_perm[s0]);
        int node1 = __ldg(&g_perm[s1]);
        ull xA0 = __ldg(&xgA[node0]), xB0 = __ldg(&xgB[node0]);
        ull xA1 = __ldg(&xgA[node1]), xB1 = __ldg(&xgB[node1]);
        ulonglong2 z0 = pb0[s0], z1 = pb0[s1];
        ull aA0 = z0.x, aB0 = z0.y, aA1 = z1.x, aB1 = z1.y;
        int dm = (d0 > d1) ? d0 : d1;
        for (int k = 0; k < dm; k++) {
            if (k < d0) {
                int2 ed = se[b0 + k];
                ull ww = pk2(__int_as_float(ed.y), __int_as_float(ed.y));
                ulonglong2 v = pb1[ed.x];
                aA0 = fma2v(v.x, ww, aA0); aB0 = fma2v(v.y, ww, aB0);
            }
            if (k < d1) {
                int2 ed = se[mid + k];
                ull ww = pk2(__int_as_float(ed.y), __int_as_float(ed.y));
                ulonglong2 v = pb1[ed.x];
                aA1 = fma2v(v.x, ww, aA1); aB1 = fma2v(v.y, ww, aB1);
            }
        }
        float ox, oy, xl, xh;
        upk2(aA0, ox, oy); upk2(xA0, xl, xh);
        ogA[node0] = make_float2(xl + ox + b20, xh + oy + b21);
        upk2(aA1, ox, oy); upk2(xA1, xl, xh);
        ogA[node1] = make_float2(xl + ox + b20, xh + oy + b21);
        if (hasB) {
            upk2(aB0, ox, oy); upk2(xB0, xl, xh);
            ogB[node0] = make_float2(xl + ox + b20, xh + oy + b21);
            upk2(aB1, ox, oy); upk2(xB1, xl, xh);
            ogB[node1] = make_float2(xl + ox + b20, xh + oy + b21);
        }
    }
    #undef GATHER2
}

// ---------------- launcher ----------------
extern "C" void kernel_launch(void* const* d_in, const int* in_sizes, int n_in,
                              void* d_out, int out_size) {
    const float* x   = (const float*)d_in[0];
    const int*   row = (const int*)  d_in[1];
    const int*   col = (const int*)  d_in[2];
    const float* ew  = (const float*)d_in[3];
    const float* W1  = (const float*)d_in[4];
    const float* b1  = (const float*)d_in[5];
    const float* W2  = (const float*)d_in[6];
    const float* b2  = (const float*)d_in[7];

    const int E = in_sizes[1];
    const int G = in_sizes[0] / (2 * NN);
    const int nCta = (G + 1) / 2;

    cudaFuncSetAttribute(k_main, cudaFuncAttributeMaxDynamicSharedMemorySize, SMEM_BYTES);

    k_pre<<<1, 1024>>>(row, col, ew, E);
    k_main<<<nCta, TPB, SMEM_BYTES>>>(x, W1, b1, W2, b2, (float*)d_out, G, E);
}